// round 4
// baseline (speedup 1.0000x reference)
#include <cuda_runtime.h>
#include <math.h>

#define Bc 4
#define Sc 2048
#define Hc 1024
#define INNERc 512
#define Rc 8

// ---------------- scratch (device globals; no allocation allowed) ----------
__device__ float g_q[Bc * Sc * Hc];      // 32 MB
__device__ float g_state[Bc * Sc * Hc];  // 32 MB
__device__ float g_tmp[Bc * Sc * Hc];    // 32 MB
__device__ float g_mu[Bc * Sc * Rc];     // mu[b][i][d-1] for edge (i, i+d)
__device__ float g_invs[Bc * Sc];
__device__ float g_dots[Bc * Sc * 9];    // d=0..8 : dot(state_i, state_{i+d})
__device__ float g_energy[Bc];

// ---------------- init ------------------------------------------------------
__global__ void copy_state_kernel(const float* __restrict__ hidden) {
    size_t i = (size_t)blockIdx.x * blockDim.x + threadIdx.x;
    if (i < (size_t)Bc * Sc * Hc / 4)
        ((float4*)g_state)[i] = ((const float4*)hidden)[i];
}

__global__ void zero_dots_kernel() {
    int i = blockIdx.x * blockDim.x + threadIdx.x;
    if (i < Bc * Sc * 9) g_dots[i] = 0.f;
}

__global__ void zero_energy_kernel() {
    if (threadIdx.x < Bc) g_energy[threadIdx.x] = 0.f;
}

// ---------------- GEMM: q = h @ Wq + bq  (M=8192, N=1024, K=1024) ----------
__global__ void gemm_kernel(const float* __restrict__ A,
                            const float* __restrict__ Bm,
                            const float* __restrict__ bias) {
    __shared__ float As[16][68];
    __shared__ float Bs[16][68];
    int bn = blockIdx.x * 64;
    int bm = blockIdx.y * 64;
    int tid = threadIdx.x;
    int arow = tid >> 2, acol = (tid & 3) << 2;
    int brow = tid >> 4, bcol = (tid & 15) << 2;
    int ty = tid >> 4, tx = tid & 15;
    float acc[4][4] = {};
    for (int k0 = 0; k0 < Hc; k0 += 16) {
        float4 a4 = *(const float4*)&A[(size_t)(bm + arow) * Hc + k0 + acol];
        As[acol + 0][arow] = a4.x;
        As[acol + 1][arow] = a4.y;
        As[acol + 2][arow] = a4.z;
        As[acol + 3][arow] = a4.w;
        float4 b4 = *(const float4*)&Bm[(size_t)(k0 + brow) * Hc + bn + bcol];
        Bs[brow][bcol + 0] = b4.x;
        Bs[brow][bcol + 1] = b4.y;
        Bs[brow][bcol + 2] = b4.z;
        Bs[brow][bcol + 3] = b4.w;
        __syncthreads();
#pragma unroll
        for (int kk = 0; kk < 16; ++kk) {
            float ra[4], rb[4];
#pragma unroll
            for (int i = 0; i < 4; ++i) ra[i] = As[kk][ty * 4 + i];
#pragma unroll
            for (int j = 0; j < 4; ++j) rb[j] = Bs[kk][tx * 4 + j];
#pragma unroll
            for (int i = 0; i < 4; ++i)
#pragma unroll
                for (int j = 0; j < 4; ++j)
                    acc[i][j] = fmaf(ra[i], rb[j], acc[i][j]);
        }
        __syncthreads();
    }
#pragma unroll
    for (int i = 0; i < 4; ++i) {
        int r = bm + ty * 4 + i;
#pragma unroll
        for (int j = 0; j < 4; ++j) {
            int c = bn + tx * 4 + j;
            g_q[(size_t)r * Hc + c] = acc[i][j] + bias[c];
        }
    }
}

// ---------------- dots: 9 sliding dot-products per node --------------------
// grid (Bc*Sc/64, Hc/128), block 256
#define DCS 64
#define DCH 128
__global__ void dots_kernel() {
    __shared__ float tile[DCS + Rc][DCH];
    int chunk = blockIdx.x;
    int b = chunk / (Sc / DCS);
    int s0 = (chunk % (Sc / DCS)) * DCS;
    int h0 = blockIdx.y * DCH;
    const float* base = g_state + (size_t)b * Sc * Hc;
    int rows = min(DCS + Rc, Sc - s0);
    for (int idx = threadIdx.x; idx < rows * (DCH / 4); idx += blockDim.x) {
        int r = idx / (DCH / 4), c4 = idx % (DCH / 4);
        float4 v = *(const float4*)&base[(size_t)(s0 + r) * Hc + h0 + c4 * 4];
        *(float4*)&tile[r][c4 * 4] = v;
    }
    __syncthreads();
    int warp = threadIdx.x >> 5, lane = threadIdx.x & 31;
    for (int task = warp; task < DCS * 9; task += (blockDim.x >> 5)) {
        int il = task / 9, d = task % 9;
        int i = s0 + il;
        if (i + d >= Sc) continue;
        float sum = 0.f;
#pragma unroll
        for (int u = 0; u < DCH / 32; ++u) {
            int c = lane + u * 32;
            sum = fmaf(tile[il][c], tile[il + d][c], sum);
        }
#pragma unroll
        for (int o = 16; o; o >>= 1) sum += __shfl_xor_sync(0xffffffffu, sum, o);
        if (lane == 0) atomicAdd(&g_dots[((size_t)b * Sc + i) * 9 + d], sum);
    }
}

// ---------------- mu: one warp per edge -------------------------------------
__global__ void mu_kernel(const float* __restrict__ W1, const float* __restrict__ b1,
                          const float* __restrict__ W2, const float* __restrict__ b2) {
    int gw = (blockIdx.x * blockDim.x + threadIdx.x) >> 5;
    int lane = threadIdx.x & 31;
    if (gw >= Bc * Sc * Rc) return;
    int dm = gw & 7;
    int i = (gw >> 3) % Sc;
    int b = gw / (Rc * Sc);
    int d = dm + 1;
    if (i + d >= Sc) return;
    const float* dots = &g_dots[(size_t)b * Sc * 9];
    float nii = dots[i * 9 + 0];
    float njj = dots[(i + d) * 9 + 0];
    float dij = dots[i * 9 + d];
    float dist = sqrtf(fmaxf(nii + njj - 2.f * dij, 0.f));
    float ni = fmaxf(sqrtf(nii), 1e-6f);
    float nj = fmaxf(sqrtf(njj), 1e-6f);
    float cosv = dij / (ni * nj);
    float acc = 0.f;
#pragma unroll
    for (int u = 0; u < INNERc / 32; ++u) {
        int m = lane + u * 32;
        float x = fmaf(dist, W1[m], fmaf(cosv, W1[INNERc + m], b1[m]));
        float g = 0.5f * x * (1.f + erff(x * 0.70710678118654752f));
        acc = fmaf(g, W2[m], acc);
    }
#pragma unroll
    for (int o = 16; o; o >>= 1) acc += __shfl_xor_sync(0xffffffffu, acc, o);
    if (lane == 0) {
        float z = acc + b2[0];
        float sp = fmaxf(z, 0.f) + log1pf(expf(-fabsf(z)));   // stable softplus
        float mu = fminf(sp + 1e-5f, 10.f);
        g_mu[((size_t)b * Sc + i) * Rc + dm] = mu;
    }
}

// ---------------- invs: deg -> max(deg,1e-6)^-0.5 ---------------------------
__global__ void invs_kernel() {
    int idx = blockIdx.x * blockDim.x + threadIdx.x;
    if (idx >= Bc * Sc) return;
    int b = idx / Sc, i = idx % Sc;
    const float* mu = &g_mu[(size_t)b * Sc * Rc];
    float deg = 0.f;
#pragma unroll
    for (int dm = 0; dm < Rc; ++dm) {
        int d = dm + 1;
        if (i + d < Sc) deg += mu[i * Rc + dm];
        if (i - d >= 0) deg += mu[(i - d) * Rc + dm];
    }
    g_invs[idx] = 1.f / sqrtf(fmaxf(deg, 1e-6f));
}

// ---------------- update: t = s - eta*(lap - q) -----------------------------
// grid (Bc*Sc/64, Hc/128), block 256
#define US 64
#define UH 128
__global__ void update_kernel(float eta) {
    __shared__ float tile[US + 2 * Rc][UH];   // 40 KB
    __shared__ float coef[US][16];
    __shared__ float cself[US];
    int chunk = blockIdx.x;
    int b = chunk / (Sc / US);
    int s0 = (chunk % (Sc / US)) * US;
    int h0 = blockIdx.y * UH;
    const float* sbase = g_state + (size_t)b * Sc * Hc;
    const float* qbase = g_q + (size_t)b * Sc * Hc;
    float* tbase = g_tmp + (size_t)b * Sc * Hc;

    for (int idx = threadIdx.x; idx < (US + 2 * Rc) * (UH / 4); idx += blockDim.x) {
        int r = idx / (UH / 4), c4 = idx % (UH / 4);
        int s = s0 - Rc + r;
        float4 v = make_float4(0.f, 0.f, 0.f, 0.f);
        if (s >= 0 && s < Sc) v = *(const float4*)&sbase[(size_t)s * Hc + h0 + c4 * 4];
        *(float4*)&tile[r][c4 * 4] = v;
    }
    const float* mu = &g_mu[(size_t)b * Sc * Rc];
    const float* invs = &g_invs[(size_t)b * Sc];
    for (int idx = threadIdx.x; idx < US * 16; idx += blockDim.x) {
        int il = idx >> 4, dd = idx & 15;
        int i = s0 + il;
        float c = 0.f;
        if (dd < 8) {
            int d = dd + 1;
            if (i + d < Sc) c = mu[i * Rc + dd] * invs[i] * invs[i + d];
        } else {
            int d = dd - 7;
            if (i - d >= 0) c = mu[(i - d) * Rc + (d - 1)] * invs[i] * invs[i - d];
        }
        coef[il][dd] = c;
    }
    __syncthreads();
    if (threadIdx.x < US) {
        float s = 0.f;
#pragma unroll
        for (int dd = 0; dd < 16; ++dd) s += coef[threadIdx.x][dd];
        cself[threadIdx.x] = s;
    }
    __syncthreads();

    int warp = threadIdx.x >> 5, lane = threadIdx.x & 31;
    for (int il = warp; il < US; il += (blockDim.x >> 5)) {
        int i = s0 + il;
        float4 s = *(float4*)&tile[il + Rc][lane * 4];
        float4 acc = make_float4(0.f, 0.f, 0.f, 0.f);
#pragma unroll
        for (int dd = 0; dd < 16; ++dd) {
            float c = coef[il][dd];
            int roff = (dd < 8) ? (dd + 1) : -(dd - 7);
            float4 n = *(float4*)&tile[il + Rc + roff][lane * 4];
            acc.x = fmaf(c, n.x, acc.x);
            acc.y = fmaf(c, n.y, acc.y);
            acc.z = fmaf(c, n.z, acc.z);
            acc.w = fmaf(c, n.w, acc.w);
        }
        float cs = cself[il];
        float4 q4 = *(const float4*)&qbase[(size_t)i * Hc + h0 + lane * 4];
        float4 t;
        t.x = s.x - eta * (cs * s.x - acc.x - q4.x);
        t.y = s.y - eta * (cs * s.y - acc.y - q4.y);
        t.z = s.z - eta * (cs * s.z - acc.z - q4.z);
        t.w = s.w - eta * (cs * s.w - acc.w - q4.w);
        *(float4*)&tbase[(size_t)i * Hc + h0 + lane * 4] = t;
    }
}

// ---------------- smooth: 3-point stencil along S ---------------------------
__global__ void smooth_kernel() {
    size_t idx = (size_t)blockIdx.x * blockDim.x + threadIdx.x;
    const int H4 = Hc / 4;
    if (idx >= (size_t)Bc * Sc * H4) return;
    int h4 = idx % H4;
    int i = (idx / H4) % Sc;
    int b = idx / ((size_t)H4 * Sc);
    const float4* t = (const float4*)g_tmp + (size_t)b * Sc * H4;
    float4 c = t[(size_t)i * H4 + h4];
    int im = max(i - 1, 0), ip = min(i + 1, Sc - 1);
    float4 l = t[(size_t)im * H4 + h4];
    float4 r = t[(size_t)ip * H4 + h4];
    float4 o;
    o.x = c.x - 0.1f * (2.f * c.x - l.x - r.x);
    o.y = c.y - 0.1f * (2.f * c.y - l.y - r.y);
    o.z = c.z - 0.1f * (2.f * c.z - l.z - r.z);
    o.w = c.w - 0.1f * (2.f * c.w - l.w - r.w);
    ((float4*)g_state)[((size_t)b * Sc + i) * H4 + h4] = o;
}

// ---------------- layernorm(state + hidden) ---------------------------------
__global__ void ln_kernel(const float* __restrict__ hidden,
                          const float* __restrict__ gamma,
                          const float* __restrict__ beta,
                          float* __restrict__ out) {
    int row = blockIdx.x;
    const float* s = g_state + (size_t)row * Hc;
    const float* h = hidden + (size_t)row * Hc;
    int tid = threadIdx.x;
    float v[4];
    float sum = 0.f, ss = 0.f;
#pragma unroll
    for (int k = 0; k < 4; ++k) {
        int c = tid + k * 256;
        float x = s[c] + h[c];
        v[k] = x;
        sum += x;
        ss += x * x;
    }
    __shared__ float r1[8], r2[8];
#pragma unroll
    for (int o = 16; o; o >>= 1) {
        sum += __shfl_xor_sync(0xffffffffu, sum, o);
        ss += __shfl_xor_sync(0xffffffffu, ss, o);
    }
    if ((tid & 31) == 0) { r1[tid >> 5] = sum; r2[tid >> 5] = ss; }
    __syncthreads();
    if (tid < 32) {
        float a = (tid < 8) ? r1[tid] : 0.f;
        float bb = (tid < 8) ? r2[tid] : 0.f;
#pragma unroll
        for (int o = 4; o; o >>= 1) {
            a += __shfl_xor_sync(0xffffffffu, a, o);
            bb += __shfl_xor_sync(0xffffffffu, bb, o);
        }
        if (tid == 0) { r1[0] = a; r2[0] = bb; }
    }
    __syncthreads();
    float mean = r1[0] * (1.f / Hc);
    float var = r2[0] * (1.f / Hc) - mean * mean;
    float is = rsqrtf(var + 1e-5f);
#pragma unroll
    for (int k = 0; k < 4; ++k) {
        int c = tid + k * 256;
        out[(size_t)row * Hc + c] = (v[k] - mean) * is * gamma[c] + beta[c];
    }
}

// ---------------- energy ----------------------------------------------------
__global__ void energy_kernel() {
    int b = blockIdx.y;
    int t = blockIdx.x * blockDim.x + threadIdx.x;
    float e = 0.f;
    if (t < Sc * Rc) {
        int dm = t & 7;
        int i = t >> 3;
        int d = dm + 1;
        if (i + d < Sc) {
            const float* dots = &g_dots[(size_t)b * Sc * 9];
            float diff2 = dots[i * 9] + dots[(i + d) * 9] - 2.f * dots[i * 9 + d];
            e = g_mu[((size_t)b * Sc + i) * Rc + dm] * diff2;
        }
    }
    __shared__ float sred[256];
    sred[threadIdx.x] = e;
    __syncthreads();
    for (int o = 128; o; o >>= 1) {
        if (threadIdx.x < o) sred[threadIdx.x] += sred[threadIdx.x + o];
        __syncthreads();
    }
    if (threadIdx.x == 0) atomicAdd(&g_energy[b], sred[0]);
}

__global__ void finalize_energy_kernel(float* __restrict__ out) {
    if (threadIdx.x < Bc)
        out[(size_t)Bc * Sc * Hc + threadIdx.x] = 0.5f * g_energy[threadIdx.x];
}

// ---------------- launch ----------------------------------------------------
extern "C" void kernel_launch(void* const* d_in, const int* in_sizes, int n_in,
                              void* d_out, int out_size) {
    const float* hidden = (const float*)d_in[0];
    // d_in[1] attention_mask (unused), d_in[2] edges (implicit window structure)
    const float* Wq = (const float*)d_in[3];
    const float* bq = (const float*)d_in[4];
    const float* W1 = (const float*)d_in[5];
    const float* b1 = (const float*)d_in[6];
    const float* W2 = (const float*)d_in[7];
    const float* b2 = (const float*)d_in[8];
    const float* gamma = (const float*)d_in[9];
    const float* beta = (const float*)d_in[10];
    float* out = (float*)d_out;

    copy_state_kernel<<<8192, 256>>>(hidden);
    gemm_kernel<<<dim3(Hc / 64, (Bc * Sc) / 64), 256>>>(hidden, Wq, bq);

    for (int k = 0; k < 4; ++k) {
        double eta_d = 0.1 * pow(0.9, (double)k);
        float eta = (float)eta_d;
        zero_dots_kernel<<<288, 256>>>();
        dots_kernel<<<dim3(Bc * Sc / DCS, Hc / DCH), 256>>>();
        mu_kernel<<<(Bc * Sc * Rc * 32) / 256, 256>>>(W1, b1, W2, b2);
        invs_kernel<<<(Bc * Sc) / 256, 256>>>();
        update_kernel<<<dim3(Bc * Sc / US, Hc / UH), 256>>>(eta);
        smooth_kernel<<<8192, 256>>>();
    }

    // final-state dots for energy
    zero_dots_kernel<<<288, 256>>>();
    dots_kernel<<<dim3(Bc * Sc / DCS, Hc / DCH), 256>>>();
    zero_energy_kernel<<<1, 32>>>();
    energy_kernel<<<dim3((Sc * Rc + 255) / 256, Bc), 256>>>();

    ln_kernel<<<Bc * Sc, 256>>>(hidden, gamma, beta, out);
    finalize_energy_kernel<<<1, 32>>>(out);
}

// round 7
// speedup vs baseline: 1.5608x; 1.5608x over previous
#include <cuda_runtime.h>
#include <cuda_bf16.h>
#include <math.h>
#include <stdint.h>

#define Bc 4
#define Sc 2048
#define Hc 1024
#define INNERc 512
#define Rc 8

// ---------------- scratch (device globals; no allocation allowed) ----------
__device__ float g_q[Bc * Sc * Hc];      // 32 MB
__device__ float g_state[Bc * Sc * Hc];  // 32 MB
__device__ float g_tmp[Bc * Sc * Hc];    // 32 MB
__device__ float g_mu[Bc * Sc * Rc];
__device__ float g_invs[Bc * Sc];
__device__ float g_dots[Bc * Sc * 9];
__device__ float g_energy[Bc];
// bf16 hi/lo split operands for the tensor-core GEMM
__device__ __nv_bfloat16 g_Acat[(size_t)Bc * Sc * 2 * Hc];  // [8192][2048] : per 32-k chunk [hi32|lo32]
__device__ __nv_bfloat16 g_Wt[(size_t)Hc * 2 * Hc];         // [1024][2048] : W^T, same chunk layout

__device__ __forceinline__ uint32_t bf2pack(__nv_bfloat16 a, __nv_bfloat16 b) {
    __nv_bfloat162 p = __halves2bfloat162(a, b);
    return *reinterpret_cast<uint32_t*>(&p);
}

// ---------------- init ------------------------------------------------------
__global__ void copy_state_kernel(const float* __restrict__ hidden) {
    size_t i = (size_t)blockIdx.x * blockDim.x + threadIdx.x;
    if (i < (size_t)Bc * Sc * Hc / 4)
        ((float4*)g_state)[i] = ((const float4*)hidden)[i];
}
__global__ void zero_energy_kernel() {
    if (threadIdx.x < Bc) g_energy[threadIdx.x] = 0.f;
}

// ---------------- fp32 -> bf16 hi/lo split of hidden ------------------------
__global__ void convertA_kernel(const float* __restrict__ hidden) {
    size_t idx = (size_t)blockIdx.x * 256 + threadIdx.x;   // over 8192*256
    int r = (int)(idx >> 8);
    int qq = (int)(idx & 255);
    int ch = qq >> 3, c4 = (qq & 7) * 4;
    float4 v = *(const float4*)&hidden[(size_t)r * Hc + ch * 32 + c4];
    float vv[4] = {v.x, v.y, v.z, v.w};
    __nv_bfloat16 h[4], l[4];
#pragma unroll
    for (int j = 0; j < 4; ++j) {
        h[j] = __float2bfloat16_rn(vv[j]);
        l[j] = __float2bfloat16_rn(vv[j] - __bfloat162float(h[j]));
    }
    size_t base = (size_t)r * 2048 + ch * 64;
    *(uint32_t*)&g_Acat[base + c4]          = bf2pack(h[0], h[1]);
    *(uint32_t*)&g_Acat[base + c4 + 2]      = bf2pack(h[2], h[3]);
    *(uint32_t*)&g_Acat[base + 32 + c4]     = bf2pack(l[0], l[1]);
    *(uint32_t*)&g_Acat[base + 32 + c4 + 2] = bf2pack(l[2], l[3]);
}

// ---------------- Wq transpose + hi/lo split --------------------------------
__global__ void convertW_kernel(const float* __restrict__ W) {
    __shared__ float tile[32][33];
    int kb = blockIdx.x, nb = blockIdx.y;
    int tx = threadIdx.x & 31, ty = threadIdx.x >> 5;   // 32 x 8
#pragma unroll
    for (int j = 0; j < 4; ++j) {
        int k = ty + j * 8;
        tile[k][tx] = W[(size_t)(kb * 32 + k) * Hc + nb * 32 + tx];
    }
    __syncthreads();
#pragma unroll
    for (int j = 0; j < 4; ++j) {
        int n = ty + j * 8;
        float x = tile[tx][n];
        __nv_bfloat16 h = __float2bfloat16_rn(x);
        __nv_bfloat16 l = __float2bfloat16_rn(x - __bfloat162float(h));
        size_t base = (size_t)(nb * 32 + n) * 2048 + kb * 64;
        g_Wt[base + tx]      = h;
        g_Wt[base + 32 + tx] = l;
    }
}

// ---------------- GEMM: q = h @ Wq + bq via mma.sync bf16 3-term split ------
// Block tile 128x128, 8 warps (4 along M x 2 along N), warp tile 32x64.
#define BM 128
#define BN 128
#define SST 72   // smem row stride (bf16) -> conflict-free fragment loads
__global__ void __launch_bounds__(256) gemm_mma_kernel(const float* __restrict__ bias) {
    __shared__ __nv_bfloat16 sA[BM * SST];   // 18.4 KB
    __shared__ __nv_bfloat16 sB[BN * SST];   // 18.4 KB
    int tid = threadIdx.x;
    int wid = tid >> 5, lane = tid & 31;
    int g = lane >> 2, tg = lane & 3;
    int wm = wid & 3, wn = wid >> 2;
    int m0 = blockIdx.y * BM, n0 = blockIdx.x * BN;
    float acc[2][8][4] = {};
    const int AO[6] = {0, 16, 32, 48, 0, 16};   // hi,hi | lo,lo | hi,hi
    const int BO[6] = {0, 16, 0, 16, 32, 48};   // hi,hi | hi,hi | lo,lo

    for (int ch = 0; ch < Hc / 32; ++ch) {
        __syncthreads();
#pragma unroll
        for (int t = 0; t < 4; ++t) {
            int idx = tid + t * 256;
            int r = idx >> 3, c8 = (idx & 7) * 8;
            *(uint4*)&sA[r * SST + c8] =
                *(const uint4*)&g_Acat[(size_t)(m0 + r) * 2048 + ch * 64 + c8];
            *(uint4*)&sB[r * SST + c8] =
                *(const uint4*)&g_Wt[(size_t)(n0 + r) * 2048 + ch * 64 + c8];
        }
        __syncthreads();
#pragma unroll
        for (int s = 0; s < 6; ++s) {
            int ka = AO[s] + 2 * tg, kb = BO[s] + 2 * tg;
            uint32_t a[2][4], b[8][2];
#pragma unroll
            for (int mt = 0; mt < 2; ++mt) {
                int row = wm * 32 + mt * 16 + g;
                a[mt][0] = *(const uint32_t*)&sA[row * SST + ka];
                a[mt][1] = *(const uint32_t*)&sA[(row + 8) * SST + ka];
                a[mt][2] = *(const uint32_t*)&sA[row * SST + ka + 8];
                a[mt][3] = *(const uint32_t*)&sA[(row + 8) * SST + ka + 8];
            }
#pragma unroll
            for (int nt = 0; nt < 8; ++nt) {
                int col = wn * 64 + nt * 8 + g;
                b[nt][0] = *(const uint32_t*)&sB[col * SST + kb];
                b[nt][1] = *(const uint32_t*)&sB[col * SST + kb + 8];
            }
#pragma unroll
            for (int mt = 0; mt < 2; ++mt)
#pragma unroll
                for (int nt = 0; nt < 8; ++nt)
                    asm volatile(
                        "mma.sync.aligned.m16n8k16.row.col.f32.bf16.bf16.f32 "
                        "{%0,%1,%2,%3}, {%4,%5,%6,%7}, {%8,%9}, {%0,%1,%2,%3};"
                        : "+f"(acc[mt][nt][0]), "+f"(acc[mt][nt][1]),
                          "+f"(acc[mt][nt][2]), "+f"(acc[mt][nt][3])
                        : "r"(a[mt][0]), "r"(a[mt][1]), "r"(a[mt][2]), "r"(a[mt][3]),
                          "r"(b[nt][0]), "r"(b[nt][1]));
        }
    }
#pragma unroll
    for (int mt = 0; mt < 2; ++mt)
#pragma unroll
        for (int nt = 0; nt < 8; ++nt) {
            int row = m0 + wm * 32 + mt * 16 + g;
            int col = n0 + wn * 64 + nt * 8 + 2 * tg;
            float2 bi = *(const float2*)&bias[col];
            float2 v0 = {acc[mt][nt][0] + bi.x, acc[mt][nt][1] + bi.y};
            float2 v1 = {acc[mt][nt][2] + bi.x, acc[mt][nt][3] + bi.y};
            *(float2*)&g_q[(size_t)row * Hc + col] = v0;
            *(float2*)&g_q[(size_t)(row + 8) * Hc + col] = v1;
        }
}

// ---------------- fused smooth + dots ---------------------------------------
// do_smooth: read g_tmp, apply 3-pt clamped smooth -> write g_state + dots of it
// else:      dots of g_state directly
#define DS 32
__global__ void __launch_bounds__(512) dots2_kernel(int do_smooth) {
    __shared__ float raw[DS + 10][128];   // rows s0-1 .. s0+40
    __shared__ float smo[DS + 8][128];    // rows s0   .. s0+39
    int blk = blockIdx.x;
    int b = blk >> 6;
    int s0 = (blk & 63) * DS;
    int warp = threadIdx.x >> 5, lane = threadIdx.x & 31;
    int r0 = warp * 2;
    const float* tbase = g_tmp + (size_t)b * Sc * Hc;
    const float* sbase = g_state + (size_t)b * Sc * Hc;
    float* stout = g_state + (size_t)b * Sc * Hc;
    float acc[2][9];
#pragma unroll
    for (int rr = 0; rr < 2; ++rr)
#pragma unroll
        for (int d = 0; d < 9; ++d) acc[rr][d] = 0.f;

    for (int hc = 0; hc < Hc / 128; ++hc) {
        int h0 = hc * 128;
        if (do_smooth) {
            for (int idx = threadIdx.x; idx < (DS + 10) * 32; idx += 512) {
                int r = idx >> 5, c4 = idx & 31;
                int s = s0 - 1 + r;
                s = s < 0 ? 0 : (s >= Sc ? Sc - 1 : s);
                *(float4*)&raw[r][c4 * 4] =
                    *(const float4*)&tbase[(size_t)s * Hc + h0 + c4 * 4];
            }
            __syncthreads();
            for (int idx = threadIdx.x; idx < (DS + 8) * 32; idx += 512) {
                int rp = idx >> 5, c4 = idx & 31;
                float4 cc = *(float4*)&raw[rp + 1][c4 * 4];
                float4 ll = *(float4*)&raw[rp][c4 * 4];
                float4 rr4 = *(float4*)&raw[rp + 2][c4 * 4];
                float4 o;
                o.x = cc.x - 0.1f * (2.f * cc.x - ll.x - rr4.x);
                o.y = cc.y - 0.1f * (2.f * cc.y - ll.y - rr4.y);
                o.z = cc.z - 0.1f * (2.f * cc.z - ll.z - rr4.z);
                o.w = cc.w - 0.1f * (2.f * cc.w - ll.w - rr4.w);
                *(float4*)&smo[rp][c4 * 4] = o;
                if (rp < DS)
                    *(float4*)&stout[(size_t)(s0 + rp) * Hc + h0 + c4 * 4] = o;
            }
            __syncthreads();
        } else {
            for (int idx = threadIdx.x; idx < (DS + 8) * 32; idx += 512) {
                int r = idx >> 5, c4 = idx & 31;
                int s = s0 + r; if (s >= Sc) s = Sc - 1;
                *(float4*)&smo[r][c4 * 4] =
                    *(const float4*)&sbase[(size_t)s * Hc + h0 + c4 * 4];
            }
            __syncthreads();
        }
#pragma unroll
        for (int u = 0; u < 4; ++u) {
            int c = lane + u * 32;
            float xv[10];
#pragma unroll
            for (int t = 0; t < 10; ++t) xv[t] = smo[r0 + t][c];
#pragma unroll
            for (int rr = 0; rr < 2; ++rr)
#pragma unroll
                for (int d = 0; d < 9; ++d)
                    acc[rr][d] = fmaf(xv[rr], xv[rr + d], acc[rr][d]);
        }
        __syncthreads();
    }
#pragma unroll
    for (int rr = 0; rr < 2; ++rr) {
        int i = s0 + r0 + rr;
#pragma unroll
        for (int d = 0; d < 9; ++d) {
            float v = acc[rr][d];
#pragma unroll
            for (int o = 16; o; o >>= 1) v += __shfl_xor_sync(0xffffffffu, v, o);
            if (lane == 0) g_dots[((size_t)b * Sc + i) * 9 + d] = v;
        }
    }
}

// ---------------- mu: one warp per edge -------------------------------------
__global__ void mu_kernel(const float* __restrict__ W1, const float* __restrict__ b1,
                          const float* __restrict__ W2, const float* __restrict__ b2) {
    int gw = (blockIdx.x * blockDim.x + threadIdx.x) >> 5;
    int lane = threadIdx.x & 31;
    if (gw >= Bc * Sc * Rc) return;
    int dm = gw & 7;
    int i = (gw >> 3) % Sc;
    int b = gw / (Rc * Sc);
    int d = dm + 1;
    if (i + d >= Sc) return;
    const float* dots = &g_dots[(size_t)b * Sc * 9];
    float nii = dots[i * 9 + 0];
    float njj = dots[(i + d) * 9 + 0];
    float dij = dots[i * 9 + d];
    float dist = sqrtf(fmaxf(nii + njj - 2.f * dij, 0.f));
    float ni = fmaxf(sqrtf(nii), 1e-6f);
    float nj = fmaxf(sqrtf(njj), 1e-6f);
    float cosv = dij / (ni * nj);
    float acc = 0.f;
#pragma unroll
    for (int u = 0; u < INNERc / 32; ++u) {
        int m = lane + u * 32;
        float x = fmaf(dist, W1[m], fmaf(cosv, W1[INNERc + m], b1[m]));
        float g = 0.5f * x * (1.f + erff(x * 0.70710678118654752f));
        acc = fmaf(g, W2[m], acc);
    }
#pragma unroll
    for (int o = 16; o; o >>= 1) acc += __shfl_xor_sync(0xffffffffu, acc, o);
    if (lane == 0) {
        float z = acc + b2[0];
        float sp = fmaxf(z, 0.f) + log1pf(expf(-fabsf(z)));
        float mu = fminf(sp + 1e-5f, 10.f);
        g_mu[((size_t)b * Sc + i) * Rc + dm] = mu;
    }
}

// ---------------- invs ------------------------------------------------------
__global__ void invs_kernel() {
    int idx = blockIdx.x * blockDim.x + threadIdx.x;
    if (idx >= Bc * Sc) return;
    int b = idx / Sc, i = idx % Sc;
    const float* mu = &g_mu[(size_t)b * Sc * Rc];
    float deg = 0.f;
#pragma unroll
    for (int dm = 0; dm < Rc; ++dm) {
        int d = dm + 1;
        if (i + d < Sc) deg += mu[i * Rc + dm];
        if (i - d >= 0) deg += mu[(i - d) * Rc + dm];
    }
    g_invs[idx] = 1.f / sqrtf(fmaxf(deg, 1e-6f));
}

// ---------------- update: t = s - eta*(lap - q) -----------------------------
#define US 64
#define UH 128
__global__ void update_kernel(float eta) {
    __shared__ float tile[US + 2 * Rc][UH];
    __shared__ float coef[US][16];
    __shared__ float cself[US];
    int chunk = blockIdx.x;
    int b = chunk / (Sc / US);
    int s0 = (chunk % (Sc / US)) * US;
    int h0 = blockIdx.y * UH;
    const float* sbase = g_state + (size_t)b * Sc * Hc;
    const float* qbase = g_q + (size_t)b * Sc * Hc;
    float* tbase = g_tmp + (size_t)b * Sc * Hc;

    for (int idx = threadIdx.x; idx < (US + 2 * Rc) * (UH / 4); idx += blockDim.x) {
        int r = idx / (UH / 4), c4 = idx % (UH / 4);
        int s = s0 - Rc + r;
        float4 v = make_float4(0.f, 0.f, 0.f, 0.f);
        if (s >= 0 && s < Sc) v = *(const float4*)&sbase[(size_t)s * Hc + h0 + c4 * 4];
        *(float4*)&tile[r][c4 * 4] = v;
    }
    const float* mu = &g_mu[(size_t)b * Sc * Rc];
    const float* invs = &g_invs[(size_t)b * Sc];
    for (int idx = threadIdx.x; idx < US * 16; idx += blockDim.x) {
        int il = idx >> 4, dd = idx & 15;
        int i = s0 + il;
        float c = 0.f;
        if (dd < 8) {
            int d = dd + 1;
            if (i + d < Sc) c = mu[i * Rc + dd] * invs[i] * invs[i + d];
        } else {
            int d = dd - 7;
            if (i - d >= 0) c = mu[(i - d) * Rc + (d - 1)] * invs[i] * invs[i - d];
        }
        coef[il][dd] = c;
    }
    __syncthreads();
    if (threadIdx.x < US) {
        float s = 0.f;
#pragma unroll
        for (int dd = 0; dd < 16; ++dd) s += coef[threadIdx.x][dd];
        cself[threadIdx.x] = s;
    }
    __syncthreads();

    int warp = threadIdx.x >> 5, lane = threadIdx.x & 31;
    for (int il = warp; il < US; il += (blockDim.x >> 5)) {
        int i = s0 + il;
        float4 s = *(float4*)&tile[il + Rc][lane * 4];
        float4 acc = make_float4(0.f, 0.f, 0.f, 0.f);
#pragma unroll
        for (int dd = 0; dd < 16; ++dd) {
            float c = coef[il][dd];
            int roff = (dd < 8) ? (dd + 1) : -(dd - 7);
            float4 n = *(float4*)&tile[il + Rc + roff][lane * 4];
            acc.x = fmaf(c, n.x, acc.x);
            acc.y = fmaf(c, n.y, acc.y);
            acc.z = fmaf(c, n.z, acc.z);
            acc.w = fmaf(c, n.w, acc.w);
        }
        float cs = cself[il];
        float4 q4 = *(const float4*)&qbase[(size_t)i * Hc + h0 + lane * 4];
        float4 t;
        t.x = s.x - eta * (cs * s.x - acc.x - q4.x);
        t.y = s.y - eta * (cs * s.y - acc.y - q4.y);
        t.z = s.z - eta * (cs * s.z - acc.z - q4.z);
        t.w = s.w - eta * (cs * s.w - acc.w - q4.w);
        *(float4*)&tbase[(size_t)i * Hc + h0 + lane * 4] = t;
    }
}

// ---------------- layernorm(state + hidden) ---------------------------------
__global__ void ln_kernel(const float* __restrict__ hidden,
                          const float* __restrict__ gamma,
                          const float* __restrict__ beta,
                          float* __restrict__ out) {
    int row = blockIdx.x;
    const float* s = g_state + (size_t)row * Hc;
    const float* h = hidden + (size_t)row * Hc;
    int tid = threadIdx.x;
    float v[4];
    float sum = 0.f, ss = 0.f;
#pragma unroll
    for (int k = 0; k < 4; ++k) {
        int c = tid + k * 256;
        float x = s[c] + h[c];
        v[k] = x;
        sum += x;
        ss += x * x;
    }
    __shared__ float r1[8], r2[8];
#pragma unroll
    for (int o = 16; o; o >>= 1) {
        sum += __shfl_xor_sync(0xffffffffu, sum, o);
        ss += __shfl_xor_sync(0xffffffffu, ss, o);
    }
    if ((tid & 31) == 0) { r1[tid >> 5] = sum; r2[tid >> 5] = ss; }
    __syncthreads();
    if (tid < 32) {
        float a = (tid < 8) ? r1[tid] : 0.f;
        float bb = (tid < 8) ? r2[tid] : 0.f;
#pragma unroll
        for (int o = 4; o; o >>= 1) {
            a += __shfl_xor_sync(0xffffffffu, a, o);
            bb += __shfl_xor_sync(0xffffffffu, bb, o);
        }
        if (tid == 0) { r1[0] = a; r2[0] = bb; }
    }
    __syncthreads();
    float mean = r1[0] * (1.f / Hc);
    float var = r2[0] * (1.f / Hc) - mean * mean;
    float is = rsqrtf(var + 1e-5f);
#pragma unroll
    for (int k = 0; k < 4; ++k) {
        int c = tid + k * 256;
        out[(size_t)row * Hc + c] = (v[k] - mean) * is * gamma[c] + beta[c];
    }
}

// ---------------- energy ----------------------------------------------------
__global__ void energy_kernel() {
    int b = blockIdx.y;
    int t = blockIdx.x * blockDim.x + threadIdx.x;
    float e = 0.f;
    if (t < Sc * Rc) {
        int dm = t & 7;
        int i = t >> 3;
        int d = dm + 1;
        if (i + d < Sc) {
            const float* dots = &g_dots[(size_t)b * Sc * 9];
            float diff2 = dots[i * 9] + dots[(i + d) * 9] - 2.f * dots[i * 9 + d];
            e = g_mu[((size_t)b * Sc + i) * Rc + dm] * diff2;
        }
    }
    __shared__ float sred[256];
    sred[threadIdx.x] = e;
    __syncthreads();
    for (int o = 128; o; o >>= 1) {
        if (threadIdx.x < o) sred[threadIdx.x] += sred[threadIdx.x + o];
        __syncthreads();
    }
    if (threadIdx.x == 0) atomicAdd(&g_energy[b], sred[0]);
}

__global__ void finalize_energy_kernel(float* __restrict__ out) {
    if (threadIdx.x < Bc)
        out[(size_t)Bc * Sc * Hc + threadIdx.x] = 0.5f * g_energy[threadIdx.x];
}

// ---------------- launch ----------------------------------------------------
extern "C" void kernel_launch(void* const* d_in, const int* in_sizes, int n_in,
                              void* d_out, int out_size) {
    const float* hidden = (const float*)d_in[0];
    const float* Wq = (const float*)d_in[3];
    const float* bq = (const float*)d_in[4];
    const float* W1 = (const float*)d_in[5];
    const float* b1 = (const float*)d_in[6];
    const float* W2 = (const float*)d_in[7];
    const float* b2 = (const float*)d_in[8];
    const float* gamma = (const float*)d_in[9];
    const float* beta = (const float*)d_in[10];
    float* out = (float*)d_out;

    copy_state_kernel<<<8192, 256>>>(hidden);
    convertA_kernel<<<8192, 256>>>(hidden);
    convertW_kernel<<<dim3(32, 32), 256>>>(Wq);
    gemm_mma_kernel<<<dim3(Hc / BN, (Bc * Sc) / BM), 256>>>(bq);

    dots2_kernel<<<Bc * (Sc / DS), 512>>>(0);
    for (int k = 0; k < 4; ++k) {
        double eta_d = 0.1 * pow(0.9, (double)k);
        float eta = (float)eta_d;
        mu_kernel<<<(Bc * Sc * Rc * 32) / 256, 256>>>(W1, b1, W2, b2);
        invs_kernel<<<(Bc * Sc) / 256, 256>>>();
        update_kernel<<<dim3(Bc * Sc / US, Hc / UH), 256>>>(eta);
        dots2_kernel<<<Bc * (Sc / DS), 512>>>(1);   // smooth + state write + dots
    }

    zero_energy_kernel<<<1, 32>>>();
    energy_kernel<<<dim3((Sc * Rc + 255) / 256, Bc), 256>>>();
    ln_kernel<<<Bc * Sc, 256>>>(hidden, gamma, beta, out);
    finalize_energy_kernel<<<1, 32>>>(out);
}

// round 8
// speedup vs baseline: 1.6567x; 1.0614x over previous
#include <cuda_runtime.h>
#include <cuda_bf16.h>
#include <math.h>
#include <stdint.h>

#define Bc 4
#define Sc 2048
#define Hc 1024
#define INNERc 512
#define Rc 8

// ---------------- scratch (device globals; no allocation allowed) ----------
__device__ float g_q[Bc * Sc * Hc];      // 32 MB
__device__ float g_state[Bc * Sc * Hc];  // 32 MB (ping)
__device__ float g_tmp[Bc * Sc * Hc];    // 32 MB (pong)
__device__ float g_mu[Bc * Sc * Rc];
__device__ float g_invs[Bc * Sc];
__device__ float g_dots[Bc * Sc * 9];
__device__ float g_energy[Bc];
__device__ __nv_bfloat16 g_Acat[(size_t)Bc * Sc * 2 * Hc];  // [8192][2048] per 32-k chunk [hi32|lo32]
__device__ __nv_bfloat16 g_Wt[(size_t)Hc * 2 * Hc];         // [1024][2048] W^T, same layout

__device__ __forceinline__ uint32_t bf2pack(__nv_bfloat16 a, __nv_bfloat16 b) {
    __nv_bfloat162 p = __halves2bfloat162(a, b);
    return *reinterpret_cast<uint32_t*>(&p);
}

// ---------------- prep: copy hidden->state AND build bf16 hi/lo split -------
__global__ void prep_kernel(const float* __restrict__ hidden) {
    size_t idx = (size_t)blockIdx.x * 256 + threadIdx.x;   // 8192*256
    int r = (int)(idx >> 8);
    int qq = (int)(idx & 255);
    int ch = qq >> 3, c4 = (qq & 7) * 4;
    size_t goff = (size_t)r * Hc + ch * 32 + c4;
    float4 v = *(const float4*)&hidden[goff];
    *(float4*)&g_state[goff] = v;
    float vv[4] = {v.x, v.y, v.z, v.w};
    __nv_bfloat16 h[4], l[4];
#pragma unroll
    for (int j = 0; j < 4; ++j) {
        h[j] = __float2bfloat16_rn(vv[j]);
        l[j] = __float2bfloat16_rn(vv[j] - __bfloat162float(h[j]));
    }
    size_t base = (size_t)r * 2048 + ch * 64;
    *(uint32_t*)&g_Acat[base + c4]          = bf2pack(h[0], h[1]);
    *(uint32_t*)&g_Acat[base + c4 + 2]      = bf2pack(h[2], h[3]);
    *(uint32_t*)&g_Acat[base + 32 + c4]     = bf2pack(l[0], l[1]);
    *(uint32_t*)&g_Acat[base + 32 + c4 + 2] = bf2pack(l[2], l[3]);
}

__global__ void zero_energy_kernel() {
    if (threadIdx.x < Bc) g_energy[threadIdx.x] = 0.f;
}

// ---------------- Wq transpose + hi/lo split --------------------------------
__global__ void convertW_kernel(const float* __restrict__ W) {
    __shared__ float tile[32][33];
    int kb = blockIdx.x, nb = blockIdx.y;
    int tx = threadIdx.x & 31, ty = threadIdx.x >> 5;   // 32 x 8
#pragma unroll
    for (int j = 0; j < 4; ++j) {
        int k = ty + j * 8;
        tile[k][tx] = W[(size_t)(kb * 32 + k) * Hc + nb * 32 + tx];
    }
    __syncthreads();
#pragma unroll
    for (int j = 0; j < 4; ++j) {
        int n = ty + j * 8;
        float x = tile[tx][n];
        __nv_bfloat16 h = __float2bfloat16_rn(x);
        __nv_bfloat16 l = __float2bfloat16_rn(x - __bfloat162float(h));
        size_t base = (size_t)(nb * 32 + n) * 2048 + kb * 64;
        g_Wt[base + tx]      = h;
        g_Wt[base + 32 + tx] = l;
    }
}

// ---------------- GEMM: q = h @ Wq + bq, mma.sync bf16 3-term split ---------
// 512 threads / 16 warps; block tile 128x128, warp tile 32x32.
// Register double-buffering: chunk ch+1 gmem loads overlap chunk ch MMAs.
#define BM 128
#define BN 128
#define SST 72   // smem row stride (bf16) -> conflict-free fragment loads
__global__ void __launch_bounds__(512) gemm_mma_kernel(const float* __restrict__ bias) {
    __shared__ __nv_bfloat16 sA[BM * SST];   // 18.4 KB
    __shared__ __nv_bfloat16 sB[BN * SST];   // 18.4 KB
    int tid = threadIdx.x;
    int wid = tid >> 5, lane = tid & 31;
    int g = lane >> 2, tg = lane & 3;
    int wm = wid & 3, wn = wid >> 2;        // 4 x 4 warps
    int m0 = blockIdx.y * BM, n0 = blockIdx.x * BN;
    float acc[2][4][4] = {};
    const int AO[6] = {0, 16, 32, 48, 0, 16};   // hi,hi | lo,lo | hi,hi
    const int BO[6] = {0, 16, 0, 16, 32, 48};   // hi,hi | hi,hi | lo,lo
    int r0 = tid >> 3, c8 = (tid & 7) * 8;      // staging coords (rows 0..63, +64)

    const __nv_bfloat16* pa0 = &g_Acat[(size_t)(m0 + r0) * 2048 + c8];
    const __nv_bfloat16* pa1 = &g_Acat[(size_t)(m0 + r0 + 64) * 2048 + c8];
    const __nv_bfloat16* pb0 = &g_Wt[(size_t)(n0 + r0) * 2048 + c8];
    const __nv_bfloat16* pb1 = &g_Wt[(size_t)(n0 + r0 + 64) * 2048 + c8];

    uint4 ra0 = *(const uint4*)pa0;
    uint4 ra1 = *(const uint4*)pa1;
    uint4 rb0 = *(const uint4*)pb0;
    uint4 rb1 = *(const uint4*)pb1;

    for (int ch = 0; ch < Hc / 32; ++ch) {
        *(uint4*)&sA[r0 * SST + c8]        = ra0;
        *(uint4*)&sA[(r0 + 64) * SST + c8] = ra1;
        *(uint4*)&sB[r0 * SST + c8]        = rb0;
        *(uint4*)&sB[(r0 + 64) * SST + c8] = rb1;
        __syncthreads();
        if (ch < Hc / 32 - 1) {                  // prefetch next chunk into regs
            int off = (ch + 1) * 64;
            ra0 = *(const uint4*)(pa0 + off);
            ra1 = *(const uint4*)(pa1 + off);
            rb0 = *(const uint4*)(pb0 + off);
            rb1 = *(const uint4*)(pb1 + off);
        }
#pragma unroll
        for (int s = 0; s < 6; ++s) {
            int ka = AO[s] + 2 * tg, kb = BO[s] + 2 * tg;
            uint32_t a[2][4], b[4][2];
#pragma unroll
            for (int mt = 0; mt < 2; ++mt) {
                int row = wm * 32 + mt * 16 + g;
                a[mt][0] = *(const uint32_t*)&sA[row * SST + ka];
                a[mt][1] = *(const uint32_t*)&sA[(row + 8) * SST + ka];
                a[mt][2] = *(const uint32_t*)&sA[row * SST + ka + 8];
                a[mt][3] = *(const uint32_t*)&sA[(row + 8) * SST + ka + 8];
            }
#pragma unroll
            for (int nt = 0; nt < 4; ++nt) {
                int col = wn * 32 + nt * 8 + g;
                b[nt][0] = *(const uint32_t*)&sB[col * SST + kb];
                b[nt][1] = *(const uint32_t*)&sB[col * SST + kb + 8];
            }
#pragma unroll
            for (int mt = 0; mt < 2; ++mt)
#pragma unroll
                for (int nt = 0; nt < 4; ++nt)
                    asm volatile(
                        "mma.sync.aligned.m16n8k16.row.col.f32.bf16.bf16.f32 "
                        "{%0,%1,%2,%3}, {%4,%5,%6,%7}, {%8,%9}, {%0,%1,%2,%3};"
                        : "+f"(acc[mt][nt][0]), "+f"(acc[mt][nt][1]),
                          "+f"(acc[mt][nt][2]), "+f"(acc[mt][nt][3])
                        : "r"(a[mt][0]), "r"(a[mt][1]), "r"(a[mt][2]), "r"(a[mt][3]),
                          "r"(b[nt][0]), "r"(b[nt][1]));
        }
        __syncthreads();
    }
#pragma unroll
    for (int mt = 0; mt < 2; ++mt)
#pragma unroll
        for (int nt = 0; nt < 4; ++nt) {
            int row = m0 + wm * 32 + mt * 16 + g;
            int col = n0 + wn * 32 + nt * 8 + 2 * tg;
            float2 bi = *(const float2*)&bias[col];
            float2 v0 = {acc[mt][nt][0] + bi.x, acc[mt][nt][1] + bi.y};
            float2 v1 = {acc[mt][nt][2] + bi.x, acc[mt][nt][3] + bi.y};
            *(float2*)&g_q[(size_t)row * Hc + col] = v0;
            *(float2*)&g_q[(size_t)(row + 8) * Hc + col] = v1;
        }
}

// ---------------- dots: 9 sliding dot-products per node (read-only) ---------
#define DS 32
__global__ void __launch_bounds__(512) dots2_kernel(const float* __restrict__ st) {
    __shared__ float smo[DS + 8][128];
    int blk = blockIdx.x;
    int b = blk >> 6;                 // Sc/DS = 64 chunks per batch
    int s0 = (blk & 63) * DS;
    int warp = threadIdx.x >> 5, lane = threadIdx.x & 31;
    int r0 = warp * 2;
    const float* sbase = st + (size_t)b * Sc * Hc;
    float acc[2][9];
#pragma unroll
    for (int rr = 0; rr < 2; ++rr)
#pragma unroll
        for (int d = 0; d < 9; ++d) acc[rr][d] = 0.f;

    for (int hc = 0; hc < Hc / 128; ++hc) {
        int h0 = hc * 128;
        for (int idx = threadIdx.x; idx < (DS + 8) * 32; idx += 512) {
            int r = idx >> 5, c4 = idx & 31;
            int s = s0 + r; if (s >= Sc) s = Sc - 1;
            *(float4*)&smo[r][c4 * 4] =
                *(const float4*)&sbase[(size_t)s * Hc + h0 + c4 * 4];
        }
        __syncthreads();
#pragma unroll
        for (int u = 0; u < 4; ++u) {
            int c = lane + u * 32;
            float xv[10];
#pragma unroll
            for (int t = 0; t < 10; ++t) xv[t] = smo[r0 + t][c];
#pragma unroll
            for (int rr = 0; rr < 2; ++rr)
#pragma unroll
                for (int d = 0; d < 9; ++d)
                    acc[rr][d] = fmaf(xv[rr], xv[rr + d], acc[rr][d]);
        }
        __syncthreads();
    }
#pragma unroll
    for (int rr = 0; rr < 2; ++rr) {
        int i = s0 + r0 + rr;
#pragma unroll
        for (int d = 0; d < 9; ++d) {
            float v = acc[rr][d];
#pragma unroll
            for (int o = 16; o; o >>= 1) v += __shfl_xor_sync(0xffffffffu, v, o);
            if (lane == 0) g_dots[((size_t)b * Sc + i) * 9 + d] = v;
        }
    }
}

// ---------------- mu: one warp per edge -------------------------------------
__global__ void mu_kernel(const float* __restrict__ W1, const float* __restrict__ b1,
                          const float* __restrict__ W2, const float* __restrict__ b2) {
    int gw = (blockIdx.x * blockDim.x + threadIdx.x) >> 5;
    int lane = threadIdx.x & 31;
    if (gw >= Bc * Sc * Rc) return;
    int dm = gw & 7;
    int i = (gw >> 3) % Sc;
    int b = gw / (Rc * Sc);
    int d = dm + 1;
    if (i + d >= Sc) return;
    const float* dots = &g_dots[(size_t)b * Sc * 9];
    float nii = dots[i * 9 + 0];
    float njj = dots[(i + d) * 9 + 0];
    float dij = dots[i * 9 + d];
    float dist = sqrtf(fmaxf(nii + njj - 2.f * dij, 0.f));
    float ni = fmaxf(sqrtf(nii), 1e-6f);
    float nj = fmaxf(sqrtf(njj), 1e-6f);
    float cosv = dij / (ni * nj);
    float acc = 0.f;
#pragma unroll
    for (int u = 0; u < INNERc / 32; ++u) {
        int m = lane + u * 32;
        float x = fmaf(dist, W1[m], fmaf(cosv, W1[INNERc + m], b1[m]));
        float g = 0.5f * x * (1.f + erff(x * 0.70710678118654752f));
        acc = fmaf(g, W2[m], acc);
    }
#pragma unroll
    for (int o = 16; o; o >>= 1) acc += __shfl_xor_sync(0xffffffffu, acc, o);
    if (lane == 0) {
        float z = acc + b2[0];
        float sp = fmaxf(z, 0.f) + log1pf(expf(-fabsf(z)));
        float mu = fminf(sp + 1e-5f, 10.f);
        g_mu[((size_t)b * Sc + i) * Rc + dm] = mu;
    }
}

// ---------------- invs ------------------------------------------------------
__global__ void invs_kernel() {
    int idx = blockIdx.x * blockDim.x + threadIdx.x;
    if (idx >= Bc * Sc) return;
    int b = idx / Sc, i = idx % Sc;
    const float* mu = &g_mu[(size_t)b * Sc * Rc];
    float deg = 0.f;
#pragma unroll
    for (int dm = 0; dm < Rc; ++dm) {
        int d = dm + 1;
        if (i + d < Sc) deg += mu[i * Rc + dm];
        if (i - d >= 0) deg += mu[(i - d) * Rc + dm];
    }
    g_invs[idx] = 1.f / sqrtf(fmaxf(deg, 1e-6f));
}

// ---------------- fused update + smooth (ping-pong in/out) ------------------
// out(i) = smooth(t)(i),  t(i) = s(i) - eta*(lap(i) - q(i)), i in [s0, s0+US2)
// needs t rows [s0-1, s0+US2] -> state rows [s0-9, s0+US2+8]
#define US2 64
#define UH2 64
__global__ void __launch_bounds__(256) upsm_kernel(const float* __restrict__ sin_,
                                                   float* __restrict__ sout,
                                                   float eta) {
    __shared__ float tile[US2 + 18][UH2];   // 82 x 64 = 21 KB
    __shared__ float tt[US2 + 2][UH2];      // 66 x 64 = 16.9 KB
    __shared__ float coef[US2 + 2][16];     // 4.2 KB
    __shared__ float cself[US2 + 2];
    int chunk = blockIdx.x;
    int b = chunk >> 5;                 // Sc/US2 = 32 chunks per batch
    int s0 = (chunk & 31) * US2;
    int h0 = blockIdx.y * UH2;
    const float* sbase = sin_ + (size_t)b * Sc * Hc;
    const float* qbase = g_q + (size_t)b * Sc * Hc;
    float* obase = sout + (size_t)b * Sc * Hc;

    for (int idx = threadIdx.x; idx < (US2 + 18) * (UH2 / 4); idx += 256) {
        int r = idx / (UH2 / 4), c4 = (idx % (UH2 / 4)) * 4;
        int s = s0 - 9 + r;
        float4 v = make_float4(0.f, 0.f, 0.f, 0.f);
        if (s >= 0 && s < Sc) v = *(const float4*)&sbase[(size_t)s * Hc + h0 + c4];
        *(float4*)&tile[r][c4] = v;
    }
    const float* mu = &g_mu[(size_t)b * Sc * Rc];
    const float* invs = &g_invs[(size_t)b * Sc];
    for (int idx = threadIdx.x; idx < (US2 + 2) * 16; idx += 256) {
        int tr = idx >> 4, dd = idx & 15;
        int i = s0 - 1 + tr;
        float c = 0.f;
        if (i >= 0 && i < Sc) {
            if (dd < 8) {
                int d = dd + 1;
                if (i + d < Sc) c = mu[i * Rc + dd] * invs[i] * invs[i + d];
            } else {
                int d = dd - 7;
                if (i - d >= 0) c = mu[(i - d) * Rc + (d - 1)] * invs[i] * invs[i - d];
            }
        }
        coef[tr][dd] = c;
    }
    __syncthreads();
    if (threadIdx.x < US2 + 2) {
        float s = 0.f;
#pragma unroll
        for (int dd = 0; dd < 16; ++dd) s += coef[threadIdx.x][dd];
        cself[threadIdx.x] = s;
    }
    __syncthreads();

    int warp = threadIdx.x >> 5, lane = threadIdx.x & 31;
    int c = lane * 2;
    for (int tr = warp; tr < US2 + 2; tr += 8) {
        int i = s0 - 1 + tr;
        if (i < 0 || i >= Sc) continue;
        float2 s = *(float2*)&tile[tr + 8][c];
        float2 a = make_float2(0.f, 0.f);
#pragma unroll
        for (int dd = 0; dd < 16; ++dd) {
            float cf = coef[tr][dd];
            int roff = (dd < 8) ? (dd + 1) : -(dd - 7);
            float2 n = *(float2*)&tile[tr + 8 + roff][c];
            a.x = fmaf(cf, n.x, a.x);
            a.y = fmaf(cf, n.y, a.y);
        }
        float cs = cself[tr];
        float2 q = *(const float2*)&qbase[(size_t)i * Hc + h0 + c];
        float2 t;
        t.x = s.x - eta * (cs * s.x - a.x - q.x);
        t.y = s.y - eta * (cs * s.y - a.y - q.y);
        *(float2*)&tt[tr][c] = t;
    }
    __syncthreads();
    for (int il = warp; il < US2; il += 8) {
        int i = s0 + il;
        int tc = il + 1;
        int tl = (i == 0) ? 1 : il;
        int trr = (i == Sc - 1) ? il + 1 : il + 2;
        float2 xc = *(float2*)&tt[tc][c];
        float2 xl = *(float2*)&tt[tl][c];
        float2 xr = *(float2*)&tt[trr][c];
        float2 o;
        o.x = xc.x - 0.1f * (2.f * xc.x - xl.x - xr.x);
        o.y = xc.y - 0.1f * (2.f * xc.y - xl.y - xr.y);
        *(float2*)&obase[(size_t)i * Hc + h0 + c] = o;
    }
}

// ---------------- layernorm(state + hidden) ---------------------------------
__global__ void ln_kernel(const float* __restrict__ hidden,
                          const float* __restrict__ gamma,
                          const float* __restrict__ beta,
                          float* __restrict__ out) {
    int row = blockIdx.x;
    const float* s = g_state + (size_t)row * Hc;
    const float* h = hidden + (size_t)row * Hc;
    int tid = threadIdx.x;
    float v[4];
    float sum = 0.f, ss = 0.f;
#pragma unroll
    for (int k = 0; k < 4; ++k) {
        int c = tid + k * 256;
        float x = s[c] + h[c];
        v[k] = x;
        sum += x;
        ss += x * x;
    }
    __shared__ float r1[8], r2[8];
#pragma unroll
    for (int o = 16; o; o >>= 1) {
        sum += __shfl_xor_sync(0xffffffffu, sum, o);
        ss += __shfl_xor_sync(0xffffffffu, ss, o);
    }
    if ((tid & 31) == 0) { r1[tid >> 5] = sum; r2[tid >> 5] = ss; }
    __syncthreads();
    if (tid < 32) {
        float a = (tid < 8) ? r1[tid] : 0.f;
        float bb = (tid < 8) ? r2[tid] : 0.f;
#pragma unroll
        for (int o = 4; o; o >>= 1) {
            a += __shfl_xor_sync(0xffffffffu, a, o);
            bb += __shfl_xor_sync(0xffffffffu, bb, o);
        }
        if (tid == 0) { r1[0] = a; r2[0] = bb; }
    }
    __syncthreads();
    float mean = r1[0] * (1.f / Hc);
    float var = r2[0] * (1.f / Hc) - mean * mean;
    float is = rsqrtf(var + 1e-5f);
#pragma unroll
    for (int k = 0; k < 4; ++k) {
        int c = tid + k * 256;
        out[(size_t)row * Hc + c] = (v[k] - mean) * is * gamma[c] + beta[c];
    }
}

// ---------------- energy ----------------------------------------------------
__global__ void energy_kernel() {
    int b = blockIdx.y;
    int t = blockIdx.x * blockDim.x + threadIdx.x;
    float e = 0.f;
    if (t < Sc * Rc) {
        int dm = t & 7;
        int i = t >> 3;
        int d = dm + 1;
        if (i + d < Sc) {
            const float* dots = &g_dots[(size_t)b * Sc * 9];
            float diff2 = dots[i * 9] + dots[(i + d) * 9] - 2.f * dots[i * 9 + d];
            e = g_mu[((size_t)b * Sc + i) * Rc + dm] * diff2;
        }
    }
    __shared__ float sred[256];
    sred[threadIdx.x] = e;
    __syncthreads();
    for (int o = 128; o; o >>= 1) {
        if (threadIdx.x < o) sred[threadIdx.x] += sred[threadIdx.x + o];
        __syncthreads();
    }
    if (threadIdx.x == 0) atomicAdd(&g_energy[b], sred[0]);
}

__global__ void finalize_energy_kernel(float* __restrict__ out) {
    if (threadIdx.x < Bc)
        out[(size_t)Bc * Sc * Hc + threadIdx.x] = 0.5f * g_energy[threadIdx.x];
}

// ---------------- launch ----------------------------------------------------
extern "C" void kernel_launch(void* const* d_in, const int* in_sizes, int n_in,
                              void* d_out, int out_size) {
    const float* hidden = (const float*)d_in[0];
    const float* Wq = (const float*)d_in[3];
    const float* bq = (const float*)d_in[4];
    const float* W1 = (const float*)d_in[5];
    const float* b1 = (const float*)d_in[6];
    const float* W2 = (const float*)d_in[7];
    const float* b2 = (const float*)d_in[8];
    const float* gamma = (const float*)d_in[9];
    const float* beta = (const float*)d_in[10];
    float* out = (float*)d_out;

    prep_kernel<<<8192, 256>>>(hidden);
    convertW_kernel<<<dim3(32, 32), 256>>>(Wq);
    gemm_mma_kernel<<<dim3(Hc / BN, (Bc * Sc) / BM), 512>>>(bq);

    // buffer ping-pong: even k reads g_state, writes g_tmp; final state -> g_state
    float* bufA;
    float* bufB;
    cudaGetSymbolAddress((void**)&bufA, g_state);
    cudaGetSymbolAddress((void**)&bufB, g_tmp);
    float* bufs[2] = {bufA, bufB};

    dots2_kernel<<<Bc * (Sc / DS), 512>>>(bufs[0]);
    for (int k = 0; k < 4; ++k) {
        double eta_d = 0.1 * pow(0.9, (double)k);
        float eta = (float)eta_d;
        mu_kernel<<<(Bc * Sc * Rc * 32) / 256, 256>>>(W1, b1, W2, b2);
        invs_kernel<<<(Bc * Sc) / 256, 256>>>();
        upsm_kernel<<<dim3(Bc * (Sc / US2), Hc / UH2), 256>>>(bufs[k & 1],
                                                              bufs[(k + 1) & 1], eta);
        dots2_kernel<<<Bc * (Sc / DS), 512>>>(bufs[(k + 1) & 1]);
    }

    zero_energy_kernel<<<1, 32>>>();
    energy_kernel<<<dim3((Sc * Rc + 255) / 256, Bc), 256>>>();
    ln_kernel<<<Bc * Sc, 256>>>(hidden, gamma, beta, out);   // final state in g_state
    finalize_energy_kernel<<<1, 32>>>(out);
}